// round 12
// baseline (speedup 1.0000x reference)
#include <cuda_runtime.h>
#include <cuda_fp16.h>
#include <cstdint>

// Problem constants
#define B_   16
#define NA_  2048
#define NB_  2048
#define D_   512
#define M_   (B_ * NA_)      // 32768 tokens

// Scratch (device globals: allocation-free per harness rules)
__device__ float    g_Pa[M_ * D_];        // feats_a @ W2 + bias     (64 MB)
__device__ float    g_Pb[M_ * D_];        // feats_b @ (W1 - W2)     (64 MB)
__device__ unsigned g_topk[M_ * 4];       // final packed keys
__device__ uint4    g_part[M_ * 4];       // partial top-4 per NB-split
// B in mma.m16n8k16 B-fragment order: [mode][kblk 0..31][npair 0..31][lane]
__device__ uint4    g_Bf[2 * 32 * 32 * 32];            // 1 MB
// A in mma.m16n8k16 A-fragment order: [mode][mt 0..2047][kblk 0..31][lane]
__device__ uint4    g_Af[2u * 2048 * 32 * 32];         // 64 MB

// ===========================================================================
// PTX helpers (baseline PTX only — compiles under compute_103)
// ===========================================================================
__device__ __forceinline__ void mma16816(float* c, const uint32_t* a, const uint32_t* b) {
    asm volatile(
        "mma.sync.aligned.m16n8k16.row.col.f32.f16.f16.f32 "
        "{%0,%1,%2,%3}, {%4,%5,%6,%7}, {%8,%9}, {%0,%1,%2,%3};"
        : "+f"(c[0]), "+f"(c[1]), "+f"(c[2]), "+f"(c[3])
        : "r"(a[0]), "r"(a[1]), "r"(a[2]), "r"(a[3]), "r"(b[0]), "r"(b[1]));
}

// ===========================================================================
// Kernel 1: prep — emit B (W2 and W1-W2) in fp16 m16n8k16 B-fragment order.
// ===========================================================================
__global__ void __launch_bounds__(256)
prep_frag_kernel(const float* __restrict__ W) {
    int t = blockIdx.x * blockDim.x + threadIdx.x;   // 0..65535
    int lane  = t & 31;
    int npair = (t >> 5) & 31;
    int kblk  = (t >> 10) & 31;
    int mode  = t >> 15;
    int K0 = kblk * 16 + (lane & 3) * 2;
    int N0 = npair * 16 + (lane >> 2);

    auto val = [&](int k, int n) -> float {
        float w2 = W[(512 + k) * 512 + n];
        return mode ? (W[k * 512 + n] - w2) : w2;
    };
    __half2 x = __floats2half2_rn(val(K0,     N0),     val(K0 + 1, N0));
    __half2 y = __floats2half2_rn(val(K0 + 8, N0),     val(K0 + 9, N0));
    __half2 z = __floats2half2_rn(val(K0,     N0 + 8), val(K0 + 1, N0 + 8));
    __half2 w = __floats2half2_rn(val(K0 + 8, N0 + 8), val(K0 + 9, N0 + 8));
    uint4 u;
    u.x = *(const uint32_t*)&x;  u.y = *(const uint32_t*)&y;
    u.z = *(const uint32_t*)&z;  u.w = *(const uint32_t*)&w;
    g_Bf[t] = u;
}

// ===========================================================================
// Kernel 1b: afrag — feats (fp32, row-major) -> fp16 A-fragments.
// m16n8k16 A layout per lane: r=lane>>2, c=(lane&3)*2;
//   a0={A[r][c],A[r][c+1]}  a1={A[r+8][c],...}  a2={A[r][c+8],...}  a3={A[r+8][c+8],...}
// Write is one uint4 per thread, perfectly coalesced.
// ===========================================================================
__global__ void __launch_bounds__(256)
afrag_kernel(const float* __restrict__ fa, const float* __restrict__ fb) {
    unsigned t = blockIdx.x * 256u + threadIdx.x;   // 0 .. 4194303
    int lane = t & 31;
    int kblk = (t >> 5) & 31;
    int mt   = (t >> 10) & 2047;
    int mode = t >> 21;
    const float* A = mode ? fb : fa;

    int r = lane >> 2;
    int c = (lane & 3) * 2;
    const float* base = A + (size_t)(mt * 16 + r) * 512 + kblk * 16 + c;
    float2 v0 = *(const float2*)(base);
    float2 v1 = *(const float2*)(base + 8 * 512);
    float2 v2 = *(const float2*)(base + 8);
    float2 v3 = *(const float2*)(base + 8 * 512 + 8);
    __half2 h0 = __floats2half2_rn(v0.x, v0.y);
    __half2 h1 = __floats2half2_rn(v1.x, v1.y);
    __half2 h2 = __floats2half2_rn(v2.x, v2.y);
    __half2 h3 = __floats2half2_rn(v3.x, v3.y);
    uint4 u;
    u.x = *(const uint32_t*)&h0;  u.y = *(const uint32_t*)&h1;
    u.z = *(const uint32_t*)&h2;  u.w = *(const uint32_t*)&h3;
    g_Af[t] = u;
}

// ===========================================================================
// Kernel 2: fused single-pass fp16 GEMM — NO smem, NO barriers.
// CTA 128x256, 8 warps 2Mx4N, warp tile 64x64. Both operands LDG'd directly
// as pre-packed MMA fragments, register double-buffered one kblk ahead.
// Warps run fully independently: the A-staging spine (LDG/CVT/STS/ldsm/bar)
// of rounds 3-11 is gone.
//   mode 0: g_Pa = feats_a @ W2 + bias  AND out[:,0:512] tile = feats_a
//   mode 1: g_Pb = feats_b @ (W1-W2)
// ===========================================================================
__global__ void __launch_bounds__(256, 1)
mma_gemm(const float* __restrict__ fa, const float* __restrict__ bias,
         float* __restrict__ out) {
    const int tid  = threadIdx.x;
    const int wid  = tid >> 5;
    const int lane = tid & 31;
    const int wm   = wid & 1;        // 2 M-slabs of 64
    const int wn   = wid >> 1;       // 4 N-slabs of 64
    const int bn   = blockIdx.x;     // 0..1  (256-col halves)
    const int bm   = blockIdx.y;     // 0..255
    const int mode = blockIdx.z;     // 0..1

    float* C = mode ? g_Pb : g_Pa;
    const int nb = bn * 256;

    // A fragments: mt0 = mode*2048 + bm*8 + wm*4 ; av[mi] at ((mi*32)+kblk)*32
    const uint4* __restrict__ Af =
        g_Af + ((size_t)(mode * 2048 + bm * 8 + wm * 4) * 32) * 32 + lane;
    // B fragments: [mode][kblk][npair][lane], npair0 = bn*16 + wn*4
    const uint4* __restrict__ Bf =
        g_Bf + ((size_t)mode * 32 * 32 + (size_t)(bn * 16 + wn * 4)) * 32 + lane;

    float c[4][8][4];
#pragma unroll
    for (int mi = 0; mi < 4; ++mi)
#pragma unroll
        for (int ni = 0; ni < 8; ++ni)
#pragma unroll
            for (int e = 0; e < 4; ++e) c[mi][ni][e] = 0.0f;

    auto load_a = [&](int kblk, uint4* av) {
#pragma unroll
        for (int mi = 0; mi < 4; ++mi)
            av[mi] = Af[(size_t)(mi * 32 + kblk) * 32];
    };
    auto load_b = [&](int kblk, uint4* bv) {
#pragma unroll
        for (int p = 0; p < 4; ++p)
            bv[p] = Bf[(size_t)kblk * 32 * 32 + p * 32];
    };

    uint4 av[4], bv[4];
    load_a(0, av);
    load_b(0, bv);

    for (int kblk = 0; kblk < 32; ++kblk) {
        uint4 an[4], bn2[4];
        if (kblk < 31) { load_a(kblk + 1, an); load_b(kblk + 1, bn2); }

        uint32_t ah[4][4];
#pragma unroll
        for (int mi = 0; mi < 4; ++mi) {
            ah[mi][0] = av[mi].x;  ah[mi][1] = av[mi].y;
            ah[mi][2] = av[mi].z;  ah[mi][3] = av[mi].w;
        }
        uint32_t bf[8][2];
#pragma unroll
        for (int p = 0; p < 4; ++p) {
            bf[p * 2][0]     = bv[p].x;  bf[p * 2][1]     = bv[p].y;
            bf[p * 2 + 1][0] = bv[p].z;  bf[p * 2 + 1][1] = bv[p].w;
        }
#pragma unroll
        for (int mi = 0; mi < 4; ++mi)
#pragma unroll
            for (int ni = 0; ni < 8; ++ni)
                mma16816(c[mi][ni], ah[mi], bf[ni]);

        if (kblk < 31) {
#pragma unroll
            for (int i = 0; i < 4; ++i) { av[i] = an[i]; bv[i] = bn2[i]; }
        }
    }

    // epilogue: store C (+bias for mode 0)
    const int g   = lane >> 2;
    const int tig = lane & 3;
#pragma unroll
    for (int mi = 0; mi < 4; ++mi) {
        const size_t row0 = (size_t)bm * 128 + wm * 64 + mi * 16 + g;
#pragma unroll
        for (int ni = 0; ni < 8; ++ni) {
            const int colg = nb + wn * 64 + ni * 8 + tig * 2;
            float2 bvz;
            if (mode == 0) bvz = *(const float2*)(bias + colg);
            else           { bvz.x = 0.0f; bvz.y = 0.0f; }
            float2 v0, v1;
            v0.x = c[mi][ni][0] + bvz.x;  v0.y = c[mi][ni][1] + bvz.y;
            v1.x = c[mi][ni][2] + bvz.x;  v1.y = c[mi][ni][3] + bvz.y;
            *(float2*)(C + row0 * 512 + colg)       = v0;
            *(float2*)(C + (row0 + 8) * 512 + colg) = v1;
        }
    }

    // mode 0: copy feats_a tile into out[:, 0:512] (DRAM headroom in GEMM)
    if (mode == 0) {
        const int crow = tid >> 1;                 // 0..127
        const int ccol = nb + (tid & 1) * 128;     // 128-col half of 256
        const float* src = fa + ((size_t)bm * 128 + crow) * 512 + ccol;
        float* dst = out + ((size_t)bm * 128 + crow) * 1024 + ccol;
#pragma unroll
        for (int i = 0; i < 32; ++i)
            *(float4*)(dst + i * 4) = *(const float4*)(src + i * 4);
    }
}

// ===========================================================================
// Kernel 3a: top-4 partials — each block scans a 512-candidate NB split.
// Key = (sq<<11) | global_j : exact (dist, idx) lexicographic order.
// ===========================================================================
__global__ void __launch_bounds__(128)
topk_part_kernel(const int* __restrict__ ca, const int* __restrict__ cb) {
    __shared__ unsigned sc[512];
    const int b     = blockIdx.y;
    const int split = blockIdx.z;
    const int a     = blockIdx.x * 128 + threadIdx.x;
    const int jbase = split * 512;

    const int* cbb = cb + ((size_t)b * NB_ + jbase) * 3;
    for (int j = threadIdx.x; j < 512; j += 128) {
        int x = cbb[j * 3 + 0];
        int y = cbb[j * 3 + 1];
        int z = cbb[j * 3 + 2];
        sc[j] = (unsigned)(x | (y << 8) | (z << 16));
    }
    __syncthreads();

    const int gi = b * NA_ + a;
    const unsigned ap = (unsigned)(ca[gi * 3 + 0] | (ca[gi * 3 + 1] << 8) |
                                   (ca[gi * 3 + 2] << 16));

    unsigned k0 = 0xFFFFFFFFu, k1 = 0xFFFFFFFFu, k2 = 0xFFFFFFFFu, k3 = 0xFFFFFFFFu;
#pragma unroll 4
    for (int j = 0; j < 512; ++j) {
        unsigned d  = __vabsdiffu4(ap, sc[j]);
        unsigned sq = __dp4a(d, d, 0u);                  // exact, <= 48387
        unsigned key = (sq << 11) | (unsigned)(jbase + j);
        if (key < k3) {
            k3 = key;
            unsigned t;
            if (k3 < k2) { t = k2; k2 = k3; k3 = t; }
            if (k2 < k1) { t = k1; k1 = k2; k2 = t; }
            if (k1 < k0) { t = k0; k0 = k1; k1 = t; }
        }
    }
    uint4 rr; rr.x = k0; rr.y = k1; rr.z = k2; rr.w = k3;
    g_part[(size_t)gi * 4 + split] = rr;
}

// ===========================================================================
// Kernel 3b: merge 4 partial top-4 lists -> final top-4.
// ===========================================================================
__global__ void __launch_bounds__(256)
topk_merge_kernel() {
    const int gi = blockIdx.x * 256 + threadIdx.x;
    unsigned k0 = 0xFFFFFFFFu, k1 = 0xFFFFFFFFu, k2 = 0xFFFFFFFFu, k3 = 0xFFFFFFFFu;
#pragma unroll
    for (int s = 0; s < 4; ++s) {
        uint4 p = g_part[(size_t)gi * 4 + s];
        unsigned v[4] = {p.x, p.y, p.z, p.w};
#pragma unroll
        for (int e = 0; e < 4; ++e) {
            unsigned key = v[e];
            if (key < k3) {
                k3 = key;
                unsigned t;
                if (k3 < k2) { t = k2; k2 = k3; k3 = t; }
                if (k2 < k1) { t = k1; k1 = k2; k2 = t; }
                if (k1 < k0) { t = k0; k0 = k1; k1 = t; }
            }
        }
    }
    uint4 rr; rr.x = k0; rr.y = k1; rr.z = k2; rr.w = k3;
    *(uint4*)&g_topk[(size_t)gi * 4] = rr;
}

// ===========================================================================
// Kernel 4: combine (fused half only; out[:,0:512] written by GEMM epilogue).
// out[t][512:] = sum_k relu(Pa[t] + Pb[idx_k]) * w_k
// ===========================================================================
__global__ void __launch_bounds__(128)
combine_kernel(float* __restrict__ out) {
    const int token = blockIdx.x;
    const int b     = token >> 11;
    const int tid   = threadIdx.x;

    uint4 keys = *(const uint4*)&g_topk[(size_t)token * 4];
    unsigned ks[4] = {keys.x, keys.y, keys.z, keys.w};
    float w[4];
    int   idx[4];
#pragma unroll
    for (int k = 0; k < 4; ++k) {
        idx[k] = (int)(ks[k] & 2047u);
        float d = sqrtf((float)(ks[k] >> 11)) * (1.0f / 128.0f);
        w[k] = fmaxf(0.5f - d, 0.0f);
    }

    const size_t rowOff = (size_t)token * D_ + tid * 4;
    float4 pa = *(const float4*)(g_Pa + rowOff);

    float4 acc; acc.x = acc.y = acc.z = acc.w = 0.0f;
    const size_t baseB = (size_t)b * NB_ * D_;
#pragma unroll
    for (int k = 0; k < 4; ++k) {
        float4 pb = *(const float4*)(g_Pb + baseB + (size_t)idx[k] * D_ + tid * 4);
        acc.x += fmaxf(pa.x + pb.x, 0.0f) * w[k];
        acc.y += fmaxf(pa.y + pb.y, 0.0f) * w[k];
        acc.z += fmaxf(pa.z + pb.z, 0.0f) * w[k];
        acc.w += fmaxf(pa.w + pb.w, 0.0f) * w[k];
    }

    *(float4*)(out + (size_t)token * 1024 + D_ + tid * 4) = acc;
}

// ===========================================================================
// Launch. Inputs: feats_a, feats_b, W, bias, coords_a, coords_b
// ===========================================================================
extern "C" void kernel_launch(void* const* d_in, const int* in_sizes, int n_in,
                              void* d_out, int out_size) {
    const float* feats_a = (const float*)d_in[0];
    const float* feats_b = (const float*)d_in[1];
    const float* W       = (const float*)d_in[2];
    const float* bias    = (const float*)d_in[3];
    const int*   ca      = (const int*)d_in[4];
    const int*   cb      = (const int*)d_in[5];
    float*       out     = (float*)d_out;

    // 1) W -> fp16 B fragments (both modes)
    prep_frag_kernel<<<256, 256>>>(W);

    // 1b) feats -> fp16 A fragments (both operands)
    afrag_kernel<<<16384, 256>>>(feats_a, feats_b);

    // 2) top-4: 4-way NB-split partials, then merge
    topk_part_kernel<<<dim3(NA_ / 128, B_, 4), 128>>>(ca, cb);
    topk_merge_kernel<<<M_ / 256, 256>>>();

    // 3) fused GEMMs, no smem / no barriers (+ feats_a passthrough copy)
    mma_gemm<<<dim3(2, 256, 2), 256>>>(feats_a, bias, out);

    // 4) combine fused half
    combine_kernel<<<M_, 128>>>(out);

    (void)in_sizes; (void)n_in; (void)out_size;
}

// round 13
// speedup vs baseline: 1.2111x; 1.2111x over previous
#include <cuda_runtime.h>
#include <cuda_fp16.h>
#include <cstdint>

// Problem constants
#define B_   16
#define NA_  2048
#define NB_  2048
#define D_   512
#define M_   (B_ * NA_)      // 32768 tokens

// Scratch (device globals: allocation-free per harness rules)
__device__ __half   g_Pah[M_ * D_];       // feats_a @ W2 + bias, fp16 (32 MB)
__device__ __half   g_Pbh[M_ * D_];       // feats_b @ (W1-W2),  fp16 (32 MB)
__device__ uint4    g_part[M_ * 4];       // partial top-4 per NB-split
// B in mma.m16n8k16 fragment order: [mode][kblk 0..31][npair 0..31][lane 0..31]
__device__ uint4    g_Bf[2 * 32 * 32 * 32];   // 1 MB

// ===========================================================================
// PTX helpers (baseline PTX only — compiles under compute_103)
// ===========================================================================
__device__ __forceinline__ uint32_t smem_u32(const void* p) {
    uint32_t a;
    asm("{ .reg .u64 t; cvta.to.shared.u64 t, %1; cvt.u32.u64 %0, t; }"
        : "=r"(a) : "l"(p));
    return a;
}
__device__ __forceinline__ void ldsm4(uint32_t addr, uint32_t* r) {
    asm volatile("ldmatrix.sync.aligned.m8n8.x4.shared.b16 {%0,%1,%2,%3}, [%4];"
                 : "=r"(r[0]), "=r"(r[1]), "=r"(r[2]), "=r"(r[3]) : "r"(addr));
}
__device__ __forceinline__ void mma16816(float* c, const uint32_t* a, const uint32_t* b) {
    asm volatile(
        "mma.sync.aligned.m16n8k16.row.col.f32.f16.f16.f32 "
        "{%0,%1,%2,%3}, {%4,%5,%6,%7}, {%8,%9}, {%0,%1,%2,%3};"
        : "+f"(c[0]), "+f"(c[1]), "+f"(c[2]), "+f"(c[3])
        : "r"(a[0]), "r"(a[1]), "r"(a[2]), "r"(a[3]), "r"(b[0]), "r"(b[1]));
}

// ===========================================================================
// Kernel 1: prep — emit B (W2 and W1-W2) in fp16 m16n8k16 B-fragment order.
// ===========================================================================
__global__ void __launch_bounds__(256)
prep_frag_kernel(const float* __restrict__ W) {
    int t = blockIdx.x * blockDim.x + threadIdx.x;   // 0..65535
    int lane  = t & 31;
    int npair = (t >> 5) & 31;
    int kblk  = (t >> 10) & 31;
    int mode  = t >> 15;
    int K0 = kblk * 16 + (lane & 3) * 2;
    int N0 = npair * 16 + (lane >> 2);

    auto val = [&](int k, int n) -> float {
        float w2 = W[(512 + k) * 512 + n];
        return mode ? (W[k * 512 + n] - w2) : w2;
    };
    __half2 x = __floats2half2_rn(val(K0,     N0),     val(K0 + 1, N0));
    __half2 y = __floats2half2_rn(val(K0 + 8, N0),     val(K0 + 9, N0));
    __half2 z = __floats2half2_rn(val(K0,     N0 + 8), val(K0 + 1, N0 + 8));
    __half2 w = __floats2half2_rn(val(K0 + 8, N0 + 8), val(K0 + 9, N0 + 8));
    uint4 u;
    u.x = *(const uint32_t*)&x;  u.y = *(const uint32_t*)&y;
    u.z = *(const uint32_t*)&z;  u.w = *(const uint32_t*)&w;
    g_Bf[t] = u;
}

// ===========================================================================
// Kernel 2: fused single-pass fp16 GEMM — EXACT round-7 champion structure.
// CTA 128x256, 8 warps 2Mx4N, warp tile 64x64. A fp32->fp16 via smem double
// buffer; B fragments LDG'd just-in-time from L2-resident table.
// ONLY change vs R7: C stored as fp16 (__half2), halving epilogue +
// downstream combine traffic.
//   mode 0: g_Pah = feats_a @ W2 + bias  AND out[:,0:512] tile = feats_a
//   mode 1: g_Pbh = feats_b @ (W1-W2)
// ===========================================================================
#define A_ROW_B  80                       // bytes per A smem row (32 fp16 + pad)
#define BUF_SZ   (128 * A_ROW_B)          // 10240 B
#define GEMM_SMEM (2 * BUF_SZ)            // 20480 B (static)

__global__ void __launch_bounds__(256, 1)
mma_gemm(const float* __restrict__ fa, const float* __restrict__ fb,
         const float* __restrict__ bias, float* __restrict__ out) {
    __shared__ __align__(16) char smem[GEMM_SMEM];
    const uint32_t sb = smem_u32(smem);

    const int tid  = threadIdx.x;
    const int wid  = tid >> 5;
    const int lane = tid & 31;
    const int wm   = wid & 1;        // 2 M-slabs of 64
    const int wn   = wid >> 1;       // 4 N-slabs of 64
    const int bn   = blockIdx.x;     // 0..1  (256-col halves)
    const int bm   = blockIdx.y;     // 0..255
    const int mode = blockIdx.z;     // 0..1

    const float* A = mode ? fb : fa;
    __half*      C = mode ? g_Pbh : g_Pah;
    const int nb = bn * 256;
    const float* Ab = A + (size_t)bm * 128 * 512;

    const int arow = tid >> 1;             // 0..127
    const int acb  = (tid & 1) * 16;       // 16 fp32 per thread

    // ldmatrix lane byte offset (conflict-free with 80B row stride)
    const int r = lane & 7, q = lane >> 3;
    const uint32_t a_lane = (uint32_t)(((q & 1) * 8 + r) * A_ROW_B + (q >> 1) * 16);

    // B fragment base: npair0 = bn*16 + wn*4 ; layout [mode][kblk][npair][lane]
    const uint4* __restrict__ Bf =
        g_Bf + ((size_t)mode * 32 * 32 + (size_t)(bn * 16 + wn * 4)) * 32 + lane;

    float c[4][8][4];
#pragma unroll
    for (int mi = 0; mi < 4; ++mi)
#pragma unroll
        for (int ni = 0; ni < 8; ++ni)
#pragma unroll
            for (int e = 0; e < 4; ++e) c[mi][ni][e] = 0.0f;

    auto load_stage = [&](int k0, float4* a4) {
        const float* ap = Ab + (size_t)arow * 512 + k0 + acb;
#pragma unroll
        for (int i = 0; i < 4; ++i) a4[i] = *(const float4*)(ap + i * 4);
    };
    auto store_stage = [&](int buf, const float4* a4) {
        char* bp = smem + buf * BUF_SZ;
#pragma unroll
        for (int i = 0; i < 4; ++i) {
            float4 v = a4[i];
            __half2 p0 = __floats2half2_rn(v.x, v.y);
            __half2 p1 = __floats2half2_rn(v.z, v.w);
            uint2 u;
            u.x = *(const uint32_t*)&p0;  u.y = *(const uint32_t*)&p1;
            *(uint2*)(bp + arow * A_ROW_B + (acb + i * 4) * 2) = u;
        }
    };

    // prologue
    {
        float4 a4[4];
        load_stage(0, a4);
        store_stage(0, a4);
    }
    __syncthreads();

    for (int s = 0; s < 16; ++s) {
        const int buf = s & 1;
        float4 a4[4];
        if (s < 15) load_stage((s + 1) * 32, a4);

        const uint32_t bpu = sb + buf * BUF_SZ;
#pragma unroll
        for (int kc = 0; kc < 2; ++kc) {
            const int kblk = s * 2 + kc;          // global 16-K block
            uint32_t ah[4][4];
#pragma unroll
            for (int mi = 0; mi < 4; ++mi) {
                uint32_t aoff = (uint32_t)((wm * 64 + mi * 16) * A_ROW_B + kc * 32) + a_lane;
                ldsm4(bpu + aoff, ah[mi]);
            }
            // 4 npairs (64 cols) of B fragments: 4 x LDG.128, L2 broadcast
            uint32_t bf[8][2];
#pragma unroll
            for (int p = 0; p < 4; ++p) {
                uint4 v = Bf[(size_t)kblk * 32 * 32 + p * 32];
                bf[p * 2][0]     = v.x;  bf[p * 2][1]     = v.y;
                bf[p * 2 + 1][0] = v.z;  bf[p * 2 + 1][1] = v.w;
            }
#pragma unroll
            for (int mi = 0; mi < 4; ++mi)
#pragma unroll
                for (int ni = 0; ni < 8; ++ni)
                    mma16816(c[mi][ni], ah[mi], bf[ni]);
        }

        if (s < 15) {
            store_stage(buf ^ 1, a4);
            __syncthreads();
        }
    }

    // epilogue: store C as fp16 (+bias for mode 0)
    const int g   = lane >> 2;
    const int tig = lane & 3;
#pragma unroll
    for (int mi = 0; mi < 4; ++mi) {
        const size_t row0 = (size_t)bm * 128 + wm * 64 + mi * 16 + g;
#pragma unroll
        for (int ni = 0; ni < 8; ++ni) {
            const int colg = nb + wn * 64 + ni * 8 + tig * 2;
            float2 bv;
            if (mode == 0) bv = *(const float2*)(bias + colg);
            else           { bv.x = 0.0f; bv.y = 0.0f; }
            __half2 h0 = __floats2half2_rn(c[mi][ni][0] + bv.x, c[mi][ni][1] + bv.y);
            __half2 h1 = __floats2half2_rn(c[mi][ni][2] + bv.x, c[mi][ni][3] + bv.y);
            *(__half2*)(C + row0 * 512 + colg)       = h0;
            *(__half2*)(C + (row0 + 8) * 512 + colg) = h1;
        }
    }

    // mode 0: copy feats_a tile into out[:, 0:512] (DRAM headroom in GEMM)
    if (mode == 0) {
        const int crow = tid >> 1;                 // 0..127
        const int ccol = nb + (tid & 1) * 128;     // 128-col half of 256
        const float* src = fa + ((size_t)bm * 128 + crow) * 512 + ccol;
        float* dst = out + ((size_t)bm * 128 + crow) * 1024 + ccol;
#pragma unroll
        for (int i = 0; i < 32; ++i)
            *(float4*)(dst + i * 4) = *(const float4*)(src + i * 4);
    }
}

// ===========================================================================
// Kernel 3: top-4 partials — each block scans a 512-candidate NB split.
// Key = (sq<<11) | global_j : exact (dist, idx) lexicographic order.
// ===========================================================================
__global__ void __launch_bounds__(128)
topk_part_kernel(const int* __restrict__ ca, const int* __restrict__ cb) {
    __shared__ unsigned sc[512];
    const int b     = blockIdx.y;
    const int split = blockIdx.z;
    const int a     = blockIdx.x * 128 + threadIdx.x;
    const int jbase = split * 512;

    const int* cbb = cb + ((size_t)b * NB_ + jbase) * 3;
    for (int j = threadIdx.x; j < 512; j += 128) {
        int x = cbb[j * 3 + 0];
        int y = cbb[j * 3 + 1];
        int z = cbb[j * 3 + 2];
        sc[j] = (unsigned)(x | (y << 8) | (z << 16));
    }
    __syncthreads();

    const int gi = b * NA_ + a;
    const unsigned ap = (unsigned)(ca[gi * 3 + 0] | (ca[gi * 3 + 1] << 8) |
                                   (ca[gi * 3 + 2] << 16));

    unsigned k0 = 0xFFFFFFFFu, k1 = 0xFFFFFFFFu, k2 = 0xFFFFFFFFu, k3 = 0xFFFFFFFFu;
#pragma unroll 4
    for (int j = 0; j < 512; ++j) {
        unsigned d  = __vabsdiffu4(ap, sc[j]);
        unsigned sq = __dp4a(d, d, 0u);                  // exact, <= 48387
        unsigned key = (sq << 11) | (unsigned)(jbase + j);
        if (key < k3) {
            k3 = key;
            unsigned t;
            if (k3 < k2) { t = k2; k2 = k3; k3 = t; }
            if (k2 < k1) { t = k1; k1 = k2; k2 = t; }
            if (k1 < k0) { t = k0; k0 = k1; k1 = t; }
        }
    }
    uint4 rr; rr.x = k0; rr.y = k1; rr.z = k2; rr.w = k3;
    g_part[(size_t)gi * 4 + split] = rr;
}

// ===========================================================================
// Kernel 4: combine with inline top-4 merge of the 4 partials.
// out[t][512:] = sum_k relu(Pa[t] + Pb[idx_k]) * w_k    (Pa/Pb fp16)
// ===========================================================================
__global__ void __launch_bounds__(128)
combine_kernel(float* __restrict__ out) {
    const int token = blockIdx.x;
    const int b     = token >> 11;
    const int tid   = threadIdx.x;

    // inline merge of 4 partial top-4 lists (broadcast loads, ~50 ALU ops)
    unsigned k0 = 0xFFFFFFFFu, k1 = 0xFFFFFFFFu, k2 = 0xFFFFFFFFu, k3 = 0xFFFFFFFFu;
#pragma unroll
    for (int s = 0; s < 4; ++s) {
        uint4 p = g_part[(size_t)token * 4 + s];
        unsigned v[4] = {p.x, p.y, p.z, p.w};
#pragma unroll
        for (int e = 0; e < 4; ++e) {
            unsigned key = v[e];
            if (key < k3) {
                k3 = key;
                unsigned t;
                if (k3 < k2) { t = k2; k2 = k3; k3 = t; }
                if (k2 < k1) { t = k1; k1 = k2; k2 = t; }
                if (k1 < k0) { t = k0; k0 = k1; k1 = t; }
            }
        }
    }

    unsigned ks[4] = {k0, k1, k2, k3};
    float w[4];
    int   idx[4];
#pragma unroll
    for (int k = 0; k < 4; ++k) {
        idx[k] = (int)(ks[k] & 2047u);
        float d = sqrtf((float)(ks[k] >> 11)) * (1.0f / 128.0f);
        w[k] = fmaxf(0.5f - d, 0.0f);
    }

    // Pa: 4 channels per thread as 2 x half2
    const size_t rowOff = (size_t)token * D_ + tid * 4;
    uint2 pav = *(const uint2*)(g_Pah + rowOff);
    __half2 pah0 = *(const __half2*)&pav.x;
    __half2 pah1 = *(const __half2*)&pav.y;
    float2 pa0 = __half22float2(pah0);
    float2 pa1 = __half22float2(pah1);

    float4 acc; acc.x = acc.y = acc.z = acc.w = 0.0f;
    const size_t baseB = (size_t)b * NB_ * D_;
#pragma unroll
    for (int k = 0; k < 4; ++k) {
        uint2 pbv = *(const uint2*)(g_Pbh + baseB + (size_t)idx[k] * D_ + tid * 4);
        float2 pb0 = __half22float2(*(const __half2*)&pbv.x);
        float2 pb1 = __half22float2(*(const __half2*)&pbv.y);
        acc.x += fmaxf(pa0.x + pb0.x, 0.0f) * w[k];
        acc.y += fmaxf(pa0.y + pb0.y, 0.0f) * w[k];
        acc.z += fmaxf(pa1.x + pb1.x, 0.0f) * w[k];
        acc.w += fmaxf(pa1.y + pb1.y, 0.0f) * w[k];
    }

    *(float4*)(out + (size_t)token * 1024 + D_ + tid * 4) = acc;
}

// ===========================================================================
// Launch. Inputs: feats_a, feats_b, W, bias, coords_a, coords_b
// ===========================================================================
extern "C" void kernel_launch(void* const* d_in, const int* in_sizes, int n_in,
                              void* d_out, int out_size) {
    const float* feats_a = (const float*)d_in[0];
    const float* feats_b = (const float*)d_in[1];
    const float* W       = (const float*)d_in[2];
    const float* bias    = (const float*)d_in[3];
    const int*   ca      = (const int*)d_in[4];
    const int*   cb      = (const int*)d_in[5];
    float*       out     = (float*)d_out;

    // 1) W -> fp16 B fragments (both modes)
    prep_frag_kernel<<<256, 256>>>(W);

    // 2) top-4: 4-way NB-split partials (merge folded into combine)
    topk_part_kernel<<<dim3(NA_ / 128, B_, 4), 128>>>(ca, cb);

    // 3) fused GEMMs (+ feats_a passthrough copy in mode-0 epilogue)
    mma_gemm<<<dim3(2, 256, 2), 256>>>(feats_a, feats_b, bias, out);

    // 4) combine fused half (inline merge, fp16 P reads)
    combine_kernel<<<M_, 128>>>(out);

    (void)in_sizes; (void)n_in; (void)out_size;
}

// round 14
// speedup vs baseline: 1.3347x; 1.1021x over previous
#include <cuda_runtime.h>
#include <cuda_fp16.h>
#include <cstdint>

// Problem constants
#define B_   16
#define NA_  2048
#define NB_  2048
#define D_   512
#define M_   (B_ * NA_)      // 32768 tokens

// Scratch (device globals: allocation-free per harness rules)
__device__ __half   g_Pah[M_ * D_];       // feats_a @ W2 + bias, fp16 (32 MB)
__device__ __half   g_Pbh[M_ * D_];       // feats_b @ (W1-W2),  fp16 (32 MB)
__device__ uint4    g_part[M_ * 4];       // partial top-4 per NB-split
__device__ uint4    g_widx[M_];           // merged neighbor indices per token
__device__ float4   g_wval[M_];           // merged neighbor weights per token
// B in mma.m16n8k16 fragment order: [mode][kblk 0..31][npair 0..31][lane 0..31]
__device__ uint4    g_Bf[2 * 32 * 32 * 32];   // 1 MB

// ===========================================================================
// PTX helpers (baseline PTX only — compiles under compute_103)
// ===========================================================================
__device__ __forceinline__ uint32_t smem_u32(const void* p) {
    uint32_t a;
    asm("{ .reg .u64 t; cvta.to.shared.u64 t, %1; cvt.u32.u64 %0, t; }"
        : "=r"(a) : "l"(p));
    return a;
}
__device__ __forceinline__ void ldsm4(uint32_t addr, uint32_t* r) {
    asm volatile("ldmatrix.sync.aligned.m8n8.x4.shared.b16 {%0,%1,%2,%3}, [%4];"
                 : "=r"(r[0]), "=r"(r[1]), "=r"(r[2]), "=r"(r[3]) : "r"(addr));
}
__device__ __forceinline__ void mma16816(float* c, const uint32_t* a, const uint32_t* b) {
    asm volatile(
        "mma.sync.aligned.m16n8k16.row.col.f32.f16.f16.f32 "
        "{%0,%1,%2,%3}, {%4,%5,%6,%7}, {%8,%9}, {%0,%1,%2,%3};"
        : "+f"(c[0]), "+f"(c[1]), "+f"(c[2]), "+f"(c[3])
        : "r"(a[0]), "r"(a[1]), "r"(a[2]), "r"(a[3]), "r"(b[0]), "r"(b[1]));
}

// ===========================================================================
// Kernel 1: prep — emit B (W2 and W1-W2) in fp16 m16n8k16 B-fragment order.
// ===========================================================================
__global__ void __launch_bounds__(256)
prep_frag_kernel(const float* __restrict__ W) {
    int t = blockIdx.x * blockDim.x + threadIdx.x;   // 0..65535
    int lane  = t & 31;
    int npair = (t >> 5) & 31;
    int kblk  = (t >> 10) & 31;
    int mode  = t >> 15;
    int K0 = kblk * 16 + (lane & 3) * 2;
    int N0 = npair * 16 + (lane >> 2);

    auto val = [&](int k, int n) -> float {
        float w2 = W[(512 + k) * 512 + n];
        return mode ? (W[k * 512 + n] - w2) : w2;
    };
    __half2 x = __floats2half2_rn(val(K0,     N0),     val(K0 + 1, N0));
    __half2 y = __floats2half2_rn(val(K0 + 8, N0),     val(K0 + 9, N0));
    __half2 z = __floats2half2_rn(val(K0,     N0 + 8), val(K0 + 1, N0 + 8));
    __half2 w = __floats2half2_rn(val(K0 + 8, N0 + 8), val(K0 + 9, N0 + 8));
    uint4 u;
    u.x = *(const uint32_t*)&x;  u.y = *(const uint32_t*)&y;
    u.z = *(const uint32_t*)&z;  u.w = *(const uint32_t*)&w;
    g_Bf[t] = u;
}

// ===========================================================================
// Kernel 2: fused single-pass fp16 GEMM — round-7 champion structure,
// fp16 C store (round-13). UNCHANGED.
//   mode 0: g_Pah = feats_a @ W2 + bias  AND out[:,0:512] tile = feats_a
//   mode 1: g_Pbh = feats_b @ (W1-W2)
// ===========================================================================
#define A_ROW_B  80                       // bytes per A smem row (32 fp16 + pad)
#define BUF_SZ   (128 * A_ROW_B)          // 10240 B
#define GEMM_SMEM (2 * BUF_SZ)            // 20480 B (static)

__global__ void __launch_bounds__(256, 1)
mma_gemm(const float* __restrict__ fa, const float* __restrict__ fb,
         const float* __restrict__ bias, float* __restrict__ out) {
    __shared__ __align__(16) char smem[GEMM_SMEM];
    const uint32_t sb = smem_u32(smem);

    const int tid  = threadIdx.x;
    const int wid  = tid >> 5;
    const int lane = tid & 31;
    const int wm   = wid & 1;        // 2 M-slabs of 64
    const int wn   = wid >> 1;       // 4 N-slabs of 64
    const int bn   = blockIdx.x;     // 0..1  (256-col halves)
    const int bm   = blockIdx.y;     // 0..255
    const int mode = blockIdx.z;     // 0..1

    const float* A = mode ? fb : fa;
    __half*      C = mode ? g_Pbh : g_Pah;
    const int nb = bn * 256;
    const float* Ab = A + (size_t)bm * 128 * 512;

    const int arow = tid >> 1;             // 0..127
    const int acb  = (tid & 1) * 16;       // 16 fp32 per thread

    // ldmatrix lane byte offset (conflict-free with 80B row stride)
    const int r = lane & 7, q = lane >> 3;
    const uint32_t a_lane = (uint32_t)(((q & 1) * 8 + r) * A_ROW_B + (q >> 1) * 16);

    // B fragment base: npair0 = bn*16 + wn*4 ; layout [mode][kblk][npair][lane]
    const uint4* __restrict__ Bf =
        g_Bf + ((size_t)mode * 32 * 32 + (size_t)(bn * 16 + wn * 4)) * 32 + lane;

    float c[4][8][4];
#pragma unroll
    for (int mi = 0; mi < 4; ++mi)
#pragma unroll
        for (int ni = 0; ni < 8; ++ni)
#pragma unroll
            for (int e = 0; e < 4; ++e) c[mi][ni][e] = 0.0f;

    auto load_stage = [&](int k0, float4* a4) {
        const float* ap = Ab + (size_t)arow * 512 + k0 + acb;
#pragma unroll
        for (int i = 0; i < 4; ++i) a4[i] = *(const float4*)(ap + i * 4);
    };
    auto store_stage = [&](int buf, const float4* a4) {
        char* bp = smem + buf * BUF_SZ;
#pragma unroll
        for (int i = 0; i < 4; ++i) {
            float4 v = a4[i];
            __half2 p0 = __floats2half2_rn(v.x, v.y);
            __half2 p1 = __floats2half2_rn(v.z, v.w);
            uint2 u;
            u.x = *(const uint32_t*)&p0;  u.y = *(const uint32_t*)&p1;
            *(uint2*)(bp + arow * A_ROW_B + (acb + i * 4) * 2) = u;
        }
    };

    // prologue
    {
        float4 a4[4];
        load_stage(0, a4);
        store_stage(0, a4);
    }
    __syncthreads();

    for (int s = 0; s < 16; ++s) {
        const int buf = s & 1;
        float4 a4[4];
        if (s < 15) load_stage((s + 1) * 32, a4);

        const uint32_t bpu = sb + buf * BUF_SZ;
#pragma unroll
        for (int kc = 0; kc < 2; ++kc) {
            const int kblk = s * 2 + kc;          // global 16-K block
            uint32_t ah[4][4];
#pragma unroll
            for (int mi = 0; mi < 4; ++mi) {
                uint32_t aoff = (uint32_t)((wm * 64 + mi * 16) * A_ROW_B + kc * 32) + a_lane;
                ldsm4(bpu + aoff, ah[mi]);
            }
            // 4 npairs (64 cols) of B fragments: 4 x LDG.128, L2 broadcast
            uint32_t bf[8][2];
#pragma unroll
            for (int p = 0; p < 4; ++p) {
                uint4 v = Bf[(size_t)kblk * 32 * 32 + p * 32];
                bf[p * 2][0]     = v.x;  bf[p * 2][1]     = v.y;
                bf[p * 2 + 1][0] = v.z;  bf[p * 2 + 1][1] = v.w;
            }
#pragma unroll
            for (int mi = 0; mi < 4; ++mi)
#pragma unroll
                for (int ni = 0; ni < 8; ++ni)
                    mma16816(c[mi][ni], ah[mi], bf[ni]);
        }

        if (s < 15) {
            store_stage(buf ^ 1, a4);
            __syncthreads();
        }
    }

    // epilogue: store C as fp16 (+bias for mode 0)
    const int g   = lane >> 2;
    const int tig = lane & 3;
#pragma unroll
    for (int mi = 0; mi < 4; ++mi) {
        const size_t row0 = (size_t)bm * 128 + wm * 64 + mi * 16 + g;
#pragma unroll
        for (int ni = 0; ni < 8; ++ni) {
            const int colg = nb + wn * 64 + ni * 8 + tig * 2;
            float2 bv;
            if (mode == 0) bv = *(const float2*)(bias + colg);
            else           { bv.x = 0.0f; bv.y = 0.0f; }
            __half2 h0 = __floats2half2_rn(c[mi][ni][0] + bv.x, c[mi][ni][1] + bv.y);
            __half2 h1 = __floats2half2_rn(c[mi][ni][2] + bv.x, c[mi][ni][3] + bv.y);
            *(__half2*)(C + row0 * 512 + colg)       = h0;
            *(__half2*)(C + (row0 + 8) * 512 + colg) = h1;
        }
    }

    // mode 0: copy feats_a tile into out[:, 0:512] (DRAM headroom in GEMM)
    if (mode == 0) {
        const int crow = tid >> 1;                 // 0..127
        const int ccol = nb + (tid & 1) * 128;     // 128-col half of 256
        const float* src = fa + ((size_t)bm * 128 + crow) * 512 + ccol;
        float* dst = out + ((size_t)bm * 128 + crow) * 1024 + ccol;
#pragma unroll
        for (int i = 0; i < 32; ++i)
            *(float4*)(dst + i * 4) = *(const float4*)(src + i * 4);
    }
}

// ===========================================================================
// Kernel 3: top-4 partials — each block scans a 512-candidate NB split.
// Key = (sq<<11) | global_j : exact (dist, idx) lexicographic order.
// ===========================================================================
__global__ void __launch_bounds__(128)
topk_part_kernel(const int* __restrict__ ca, const int* __restrict__ cb) {
    __shared__ unsigned sc[512];
    const int b     = blockIdx.y;
    const int split = blockIdx.z;
    const int a     = blockIdx.x * 128 + threadIdx.x;
    const int jbase = split * 512;

    const int* cbb = cb + ((size_t)b * NB_ + jbase) * 3;
    for (int j = threadIdx.x; j < 512; j += 128) {
        int x = cbb[j * 3 + 0];
        int y = cbb[j * 3 + 1];
        int z = cbb[j * 3 + 2];
        sc[j] = (unsigned)(x | (y << 8) | (z << 16));
    }
    __syncthreads();

    const int gi = b * NA_ + a;
    const unsigned ap = (unsigned)(ca[gi * 3 + 0] | (ca[gi * 3 + 1] << 8) |
                                   (ca[gi * 3 + 2] << 16));

    unsigned k0 = 0xFFFFFFFFu, k1 = 0xFFFFFFFFu, k2 = 0xFFFFFFFFu, k3 = 0xFFFFFFFFu;
#pragma unroll 4
    for (int j = 0; j < 512; ++j) {
        unsigned d  = __vabsdiffu4(ap, sc[j]);
        unsigned sq = __dp4a(d, d, 0u);                  // exact, <= 48387
        unsigned key = (sq << 11) | (unsigned)(jbase + j);
        if (key < k3) {
            k3 = key;
            unsigned t;
            if (k3 < k2) { t = k2; k2 = k3; k3 = t; }
            if (k2 < k1) { t = k1; k1 = k2; k2 = t; }
            if (k1 < k0) { t = k0; k0 = k1; k1 = t; }
        }
    }
    uint4 rr; rr.x = k0; rr.y = k1; rr.z = k2; rr.w = k3;
    g_part[(size_t)gi * 4 + split] = rr;
}

// ===========================================================================
// Kernel 3b: wprep — merge 4 partial top-4 lists, emit idx[4] + w[4] per
// token ONCE (removes redundant per-channel-thread merge ALU from combine).
// ===========================================================================
__global__ void __launch_bounds__(256)
wprep_kernel() {
    const int gi = blockIdx.x * 256 + threadIdx.x;
    unsigned k0 = 0xFFFFFFFFu, k1 = 0xFFFFFFFFu, k2 = 0xFFFFFFFFu, k3 = 0xFFFFFFFFu;
#pragma unroll
    for (int s = 0; s < 4; ++s) {
        uint4 p = g_part[(size_t)gi * 4 + s];
        unsigned v[4] = {p.x, p.y, p.z, p.w};
#pragma unroll
        for (int e = 0; e < 4; ++e) {
            unsigned key = v[e];
            if (key < k3) {
                k3 = key;
                unsigned t;
                if (k3 < k2) { t = k2; k2 = k3; k3 = t; }
                if (k2 < k1) { t = k1; k1 = k2; k2 = t; }
                if (k1 < k0) { t = k0; k0 = k1; k1 = t; }
            }
        }
    }
    unsigned ks[4] = {k0, k1, k2, k3};
    uint4 iv; float4 wv;
    unsigned* ip = &iv.x;  float* wp = &wv.x;
#pragma unroll
    for (int k = 0; k < 4; ++k) {
        ip[k] = ks[k] & 2047u;
        float d = sqrtf((float)(ks[k] >> 11)) * (1.0f / 128.0f);
        wp[k] = fmaxf(0.5f - d, 0.0f);
    }
    g_widx[gi] = iv;
    g_wval[gi] = wv;
}

// ===========================================================================
// Kernel 4: combine — pure gather + relu + weighted sum (fp16 P reads).
// out[t][512:] = sum_k relu(Pa[t] + Pb[idx_k]) * w_k
// ===========================================================================
__global__ void __launch_bounds__(128)
combine_kernel(float* __restrict__ out) {
    const int token = blockIdx.x;
    const int b     = token >> 11;
    const int tid   = threadIdx.x;

    uint4  iv = g_widx[token];      // broadcast loads
    float4 wv = g_wval[token];
    const unsigned idx[4] = {iv.x, iv.y, iv.z, iv.w};
    const float    w[4]   = {wv.x, wv.y, wv.z, wv.w};

    const size_t rowOff = (size_t)token * D_ + tid * 4;
    uint2 pav = *(const uint2*)(g_Pah + rowOff);
    float2 pa0 = __half22float2(*(const __half2*)&pav.x);
    float2 pa1 = __half22float2(*(const __half2*)&pav.y);

    float4 acc; acc.x = acc.y = acc.z = acc.w = 0.0f;
    const size_t baseB = (size_t)b * NB_ * D_;
#pragma unroll
    for (int k = 0; k < 4; ++k) {
        uint2 pbv = *(const uint2*)(g_Pbh + baseB + (size_t)idx[k] * D_ + tid * 4);
        float2 pb0 = __half22float2(*(const __half2*)&pbv.x);
        float2 pb1 = __half22float2(*(const __half2*)&pbv.y);
        acc.x += fmaxf(pa0.x + pb0.x, 0.0f) * w[k];
        acc.y += fmaxf(pa0.y + pb0.y, 0.0f) * w[k];
        acc.z += fmaxf(pa1.x + pb1.x, 0.0f) * w[k];
        acc.w += fmaxf(pa1.y + pb1.y, 0.0f) * w[k];
    }

    *(float4*)(out + (size_t)token * 1024 + D_ + tid * 4) = acc;
}

// ===========================================================================
// Launch. Inputs: feats_a, feats_b, W, bias, coords_a, coords_b
// Stream fork-join: topk (ALU-bound, tiny footprint) overlaps the GEMM
// (tensor-bound) — co-resident per SM. Capture-safe event fork pattern.
// ===========================================================================
extern "C" void kernel_launch(void* const* d_in, const int* in_sizes, int n_in,
                              void* d_out, int out_size) {
    const float* feats_a = (const float*)d_in[0];
    const float* feats_b = (const float*)d_in[1];
    const float* W       = (const float*)d_in[2];
    const float* bias    = (const float*)d_in[3];
    const int*   ca      = (const int*)d_in[4];
    const int*   cb      = (const int*)d_in[5];
    float*       out     = (float*)d_out;

    // one-time resources (created on the uncaptured correctness call)
    static cudaStream_t s1 = nullptr;
    static cudaEvent_t  evFork = nullptr, evJoin = nullptr;
    if (s1 == nullptr) {
        cudaStreamCreateWithFlags(&s1, cudaStreamNonBlocking);
        cudaEventCreateWithFlags(&evFork, cudaEventDisableTiming);
        cudaEventCreateWithFlags(&evJoin, cudaEventDisableTiming);
    }

    // fork: side stream runs topk_part + wprep concurrently with prep+GEMM
    cudaEventRecord(evFork, 0);
    cudaStreamWaitEvent(s1, evFork, 0);

    topk_part_kernel<<<dim3(NA_ / 128, B_, 4), 128, 0, s1>>>(ca, cb);
    wprep_kernel<<<M_ / 256, 256, 0, s1>>>();
    cudaEventRecord(evJoin, s1);

    // main stream: W fragments, then the fused GEMMs
    prep_frag_kernel<<<256, 256>>>(W);
    mma_gemm<<<dim3(2, 256, 2), 256>>>(feats_a, feats_b, bias, out);

    // join, then combine (needs GEMM outputs + wprep results)
    cudaStreamWaitEvent(0, evJoin, 0);
    combine_kernel<<<M_, 128>>>(out);

    (void)in_sizes; (void)n_in; (void)out_size;
}

// round 15
// speedup vs baseline: 1.4678x; 1.0997x over previous
#include <cuda_runtime.h>
#include <cuda_fp16.h>
#include <cstdint>

// Problem constants
#define B_   16
#define NA_  2048
#define NB_  2048
#define D_   512
#define M_   (B_ * NA_)      // 32768 tokens

// Scratch (device globals: allocation-free per harness rules)
__device__ __half   g_Pah[M_ * D_];       // feats_a @ W2 + bias, fp16 (32 MB)
__device__ __half   g_Pbh[M_ * D_];       // feats_b @ (W1-W2),  fp16 (32 MB)
__device__ uint4    g_part[M_ * 4];       // partial top-4 per NB-split
__device__ uint4    g_widx[M_];           // merged neighbor indices per token
__device__ float4   g_wval[M_];           // merged neighbor weights per token
// B in mma.m16n8k16 fragment order: [mode][kblk 0..31][npair 0..31][lane 0..31]
__device__ uint4    g_Bf[2 * 32 * 32 * 32];   // 1 MB

// ===========================================================================
// PTX helpers (baseline PTX only — compiles under compute_103)
// ===========================================================================
__device__ __forceinline__ uint32_t smem_u32(const void* p) {
    uint32_t a;
    asm("{ .reg .u64 t; cvta.to.shared.u64 t, %1; cvt.u32.u64 %0, t; }"
        : "=r"(a) : "l"(p));
    return a;
}
__device__ __forceinline__ void ldsm4(uint32_t addr, uint32_t* r) {
    asm volatile("ldmatrix.sync.aligned.m8n8.x4.shared.b16 {%0,%1,%2,%3}, [%4];"
                 : "=r"(r[0]), "=r"(r[1]), "=r"(r[2]), "=r"(r[3]) : "r"(addr));
}
__device__ __forceinline__ void mma16816(float* c, const uint32_t* a, const uint32_t* b) {
    asm volatile(
        "mma.sync.aligned.m16n8k16.row.col.f32.f16.f16.f32 "
        "{%0,%1,%2,%3}, {%4,%5,%6,%7}, {%8,%9}, {%0,%1,%2,%3};"
        : "+f"(c[0]), "+f"(c[1]), "+f"(c[2]), "+f"(c[3])
        : "r"(a[0]), "r"(a[1]), "r"(a[2]), "r"(a[3]), "r"(b[0]), "r"(b[1]));
}

// ===========================================================================
// Kernel 1: prep — emit B (W2 and W1-W2) in fp16 m16n8k16 B-fragment order.
// ===========================================================================
__global__ void __launch_bounds__(256)
prep_frag_kernel(const float* __restrict__ W) {
    int t = blockIdx.x * blockDim.x + threadIdx.x;   // 0..65535
    int lane  = t & 31;
    int npair = (t >> 5) & 31;
    int kblk  = (t >> 10) & 31;
    int mode  = t >> 15;
    int K0 = kblk * 16 + (lane & 3) * 2;
    int N0 = npair * 16 + (lane >> 2);

    auto val = [&](int k, int n) -> float {
        float w2 = W[(512 + k) * 512 + n];
        return mode ? (W[k * 512 + n] - w2) : w2;
    };
    __half2 x = __floats2half2_rn(val(K0,     N0),     val(K0 + 1, N0));
    __half2 y = __floats2half2_rn(val(K0 + 8, N0),     val(K0 + 9, N0));
    __half2 z = __floats2half2_rn(val(K0,     N0 + 8), val(K0 + 1, N0 + 8));
    __half2 w = __floats2half2_rn(val(K0 + 8, N0 + 8), val(K0 + 9, N0 + 8));
    uint4 u;
    u.x = *(const uint32_t*)&x;  u.y = *(const uint32_t*)&y;
    u.z = *(const uint32_t*)&z;  u.w = *(const uint32_t*)&w;
    g_Bf[t] = u;
}

// ===========================================================================
// Kernel 2: fused single-pass fp16 GEMM — round-7 champion structure,
// fp16 C store. Passthrough copy REMOVED from epilogue (own kernel, side
// stream) — epilogue tail shortens.
//   mode 0: g_Pah = feats_a @ W2 + bias
//   mode 1: g_Pbh = feats_b @ (W1-W2)
// ===========================================================================
#define A_ROW_B  80                       // bytes per A smem row (32 fp16 + pad)
#define BUF_SZ   (128 * A_ROW_B)          // 10240 B
#define GEMM_SMEM (2 * BUF_SZ)            // 20480 B (static)

__global__ void __launch_bounds__(256, 1)
mma_gemm(const float* __restrict__ fa, const float* __restrict__ fb,
         const float* __restrict__ bias) {
    __shared__ __align__(16) char smem[GEMM_SMEM];
    const uint32_t sb = smem_u32(smem);

    const int tid  = threadIdx.x;
    const int wid  = tid >> 5;
    const int lane = tid & 31;
    const int wm   = wid & 1;        // 2 M-slabs of 64
    const int wn   = wid >> 1;       // 4 N-slabs of 64
    const int bn   = blockIdx.x;     // 0..1  (256-col halves)
    const int bm   = blockIdx.y;     // 0..255
    const int mode = blockIdx.z;     // 0..1

    const float* A = mode ? fb : fa;
    __half*      C = mode ? g_Pbh : g_Pah;
    const int nb = bn * 256;
    const float* Ab = A + (size_t)bm * 128 * 512;

    const int arow = tid >> 1;             // 0..127
    const int acb  = (tid & 1) * 16;       // 16 fp32 per thread

    // ldmatrix lane byte offset (conflict-free with 80B row stride)
    const int r = lane & 7, q = lane >> 3;
    const uint32_t a_lane = (uint32_t)(((q & 1) * 8 + r) * A_ROW_B + (q >> 1) * 16);

    // B fragment base: npair0 = bn*16 + wn*4 ; layout [mode][kblk][npair][lane]
    const uint4* __restrict__ Bf =
        g_Bf + ((size_t)mode * 32 * 32 + (size_t)(bn * 16 + wn * 4)) * 32 + lane;

    float c[4][8][4];
#pragma unroll
    for (int mi = 0; mi < 4; ++mi)
#pragma unroll
        for (int ni = 0; ni < 8; ++ni)
#pragma unroll
            for (int e = 0; e < 4; ++e) c[mi][ni][e] = 0.0f;

    auto load_stage = [&](int k0, float4* a4) {
        const float* ap = Ab + (size_t)arow * 512 + k0 + acb;
#pragma unroll
        for (int i = 0; i < 4; ++i) a4[i] = *(const float4*)(ap + i * 4);
    };
    auto store_stage = [&](int buf, const float4* a4) {
        char* bp = smem + buf * BUF_SZ;
#pragma unroll
        for (int i = 0; i < 4; ++i) {
            float4 v = a4[i];
            __half2 p0 = __floats2half2_rn(v.x, v.y);
            __half2 p1 = __floats2half2_rn(v.z, v.w);
            uint2 u;
            u.x = *(const uint32_t*)&p0;  u.y = *(const uint32_t*)&p1;
            *(uint2*)(bp + arow * A_ROW_B + (acb + i * 4) * 2) = u;
        }
    };

    // prologue
    {
        float4 a4[4];
        load_stage(0, a4);
        store_stage(0, a4);
    }
    __syncthreads();

    for (int s = 0; s < 16; ++s) {
        const int buf = s & 1;
        float4 a4[4];
        if (s < 15) load_stage((s + 1) * 32, a4);

        const uint32_t bpu = sb + buf * BUF_SZ;
#pragma unroll
        for (int kc = 0; kc < 2; ++kc) {
            const int kblk = s * 2 + kc;          // global 16-K block
            uint32_t ah[4][4];
#pragma unroll
            for (int mi = 0; mi < 4; ++mi) {
                uint32_t aoff = (uint32_t)((wm * 64 + mi * 16) * A_ROW_B + kc * 32) + a_lane;
                ldsm4(bpu + aoff, ah[mi]);
            }
            // 4 npairs (64 cols) of B fragments: 4 x LDG.128, L2 broadcast
            uint32_t bf[8][2];
#pragma unroll
            for (int p = 0; p < 4; ++p) {
                uint4 v = Bf[(size_t)kblk * 32 * 32 + p * 32];
                bf[p * 2][0]     = v.x;  bf[p * 2][1]     = v.y;
                bf[p * 2 + 1][0] = v.z;  bf[p * 2 + 1][1] = v.w;
            }
#pragma unroll
            for (int mi = 0; mi < 4; ++mi)
#pragma unroll
                for (int ni = 0; ni < 8; ++ni)
                    mma16816(c[mi][ni], ah[mi], bf[ni]);
        }

        if (s < 15) {
            store_stage(buf ^ 1, a4);
            __syncthreads();
        }
    }

    // epilogue: store C as fp16 (+bias for mode 0)
    const int g   = lane >> 2;
    const int tig = lane & 3;
#pragma unroll
    for (int mi = 0; mi < 4; ++mi) {
        const size_t row0 = (size_t)bm * 128 + wm * 64 + mi * 16 + g;
#pragma unroll
        for (int ni = 0; ni < 8; ++ni) {
            const int colg = nb + wn * 64 + ni * 8 + tig * 2;
            float2 bv;
            if (mode == 0) bv = *(const float2*)(bias + colg);
            else           { bv.x = 0.0f; bv.y = 0.0f; }
            __half2 h0 = __floats2half2_rn(c[mi][ni][0] + bv.x, c[mi][ni][1] + bv.y);
            __half2 h1 = __floats2half2_rn(c[mi][ni][2] + bv.x, c[mi][ni][3] + bv.y);
            *(__half2*)(C + row0 * 512 + colg)       = h0;
            *(__half2*)(C + (row0 + 8) * 512 + colg) = h1;
        }
    }
}

// ===========================================================================
// Kernel 2b: passthrough — out[t][0:512] = feats_a[t]. Pure stream copy,
// runs on the side stream concurrently with the GEMM (disjoint out halves).
// ===========================================================================
__global__ void __launch_bounds__(256)
passthru_kernel(const float* __restrict__ fa, float* __restrict__ out) {
    unsigned i = blockIdx.x * 256u + threadIdx.x;   // float4 index, 4M total
    unsigned token = i >> 7;                        // 128 float4 per token
    unsigned c4    = i & 127;
    float4 v = *(const float4*)(fa + (size_t)token * 512 + c4 * 4);
    *(float4*)(out + (size_t)token * 1024 + c4 * 4) = v;
}

// ===========================================================================
// Kernel 3: top-4 partials — each block scans a 512-candidate NB split.
// Key = (sq<<11) | global_j : exact (dist, idx) lexicographic order.
// ===========================================================================
__global__ void __launch_bounds__(128)
topk_part_kernel(const int* __restrict__ ca, const int* __restrict__ cb) {
    __shared__ unsigned sc[512];
    const int b     = blockIdx.y;
    const int split = blockIdx.z;
    const int a     = blockIdx.x * 128 + threadIdx.x;
    const int jbase = split * 512;

    const int* cbb = cb + ((size_t)b * NB_ + jbase) * 3;
    for (int j = threadIdx.x; j < 512; j += 128) {
        int x = cbb[j * 3 + 0];
        int y = cbb[j * 3 + 1];
        int z = cbb[j * 3 + 2];
        sc[j] = (unsigned)(x | (y << 8) | (z << 16));
    }
    __syncthreads();

    const int gi = b * NA_ + a;
    const unsigned ap = (unsigned)(ca[gi * 3 + 0] | (ca[gi * 3 + 1] << 8) |
                                   (ca[gi * 3 + 2] << 16));

    unsigned k0 = 0xFFFFFFFFu, k1 = 0xFFFFFFFFu, k2 = 0xFFFFFFFFu, k3 = 0xFFFFFFFFu;
#pragma unroll 4
    for (int j = 0; j < 512; ++j) {
        unsigned d  = __vabsdiffu4(ap, sc[j]);
        unsigned sq = __dp4a(d, d, 0u);                  // exact, <= 48387
        unsigned key = (sq << 11) | (unsigned)(jbase + j);
        if (key < k3) {
            k3 = key;
            unsigned t;
            if (k3 < k2) { t = k2; k2 = k3; k3 = t; }
            if (k2 < k1) { t = k1; k1 = k2; k2 = t; }
            if (k1 < k0) { t = k0; k0 = k1; k1 = t; }
        }
    }
    uint4 rr; rr.x = k0; rr.y = k1; rr.z = k2; rr.w = k3;
    g_part[(size_t)gi * 4 + split] = rr;
}

// ===========================================================================
// Kernel 3b: wprep — merge 4 partial top-4 lists, emit idx[4] + w[4].
// ===========================================================================
__global__ void __launch_bounds__(256)
wprep_kernel() {
    const int gi = blockIdx.x * 256 + threadIdx.x;
    unsigned k0 = 0xFFFFFFFFu, k1 = 0xFFFFFFFFu, k2 = 0xFFFFFFFFu, k3 = 0xFFFFFFFFu;
#pragma unroll
    for (int s = 0; s < 4; ++s) {
        uint4 p = g_part[(size_t)gi * 4 + s];
        unsigned v[4] = {p.x, p.y, p.z, p.w};
#pragma unroll
        for (int e = 0; e < 4; ++e) {
            unsigned key = v[e];
            if (key < k3) {
                k3 = key;
                unsigned t;
                if (k3 < k2) { t = k2; k2 = k3; k3 = t; }
                if (k2 < k1) { t = k1; k1 = k2; k2 = t; }
                if (k1 < k0) { t = k0; k0 = k1; k1 = t; }
            }
        }
    }
    unsigned ks[4] = {k0, k1, k2, k3};
    uint4 iv; float4 wv;
    unsigned* ip = &iv.x;  float* wp = &wv.x;
#pragma unroll
    for (int k = 0; k < 4; ++k) {
        ip[k] = ks[k] & 2047u;
        float d = sqrtf((float)(ks[k] >> 11)) * (1.0f / 128.0f);
        wp[k] = fmaxf(0.5f - d, 0.0f);
    }
    g_widx[gi] = iv;
    g_wval[gi] = wv;
}

// ===========================================================================
// Kernel 4: combine — gather + relu + weighted sum (fp16 P reads).
// 256 threads / block, 2 tokens per block.
// out[t][512:] = sum_k relu(Pa[t] + Pb[idx_k]) * w_k
// ===========================================================================
__global__ void __launch_bounds__(256)
combine_kernel(float* __restrict__ out) {
    const int token = blockIdx.x * 2 + (threadIdx.x >> 7);
    const int b     = token >> 11;
    const int tid   = threadIdx.x & 127;

    uint4  iv = g_widx[token];      // broadcast loads (per half-block)
    float4 wv = g_wval[token];
    const unsigned idx[4] = {iv.x, iv.y, iv.z, iv.w};
    const float    w[4]   = {wv.x, wv.y, wv.z, wv.w};

    const size_t rowOff = (size_t)token * D_ + tid * 4;
    uint2 pav = *(const uint2*)(g_Pah + rowOff);
    float2 pa0 = __half22float2(*(const __half2*)&pav.x);
    float2 pa1 = __half22float2(*(const __half2*)&pav.y);

    float4 acc; acc.x = acc.y = acc.z = acc.w = 0.0f;
    const size_t baseB = (size_t)b * NB_ * D_;
#pragma unroll
    for (int k = 0; k < 4; ++k) {
        uint2 pbv = *(const uint2*)(g_Pbh + baseB + (size_t)idx[k] * D_ + tid * 4);
        float2 pb0 = __half22float2(*(const __half2*)&pbv.x);
        float2 pb1 = __half22float2(*(const __half2*)&pbv.y);
        acc.x += fmaxf(pa0.x + pb0.x, 0.0f) * w[k];
        acc.y += fmaxf(pa0.y + pb0.y, 0.0f) * w[k];
        acc.z += fmaxf(pa1.x + pb1.x, 0.0f) * w[k];
        acc.w += fmaxf(pa1.y + pb1.y, 0.0f) * w[k];
    }

    *(float4*)(out + (size_t)token * 1024 + D_ + tid * 4) = acc;
}

// ===========================================================================
// Launch. Inputs: feats_a, feats_b, W, bias, coords_a, coords_b
// Fork-join: side stream runs topk + wprep + passthrough copy, all hidden
// under the GEMM on the main stream. Capture-safe event pattern.
// ===========================================================================
extern "C" void kernel_launch(void* const* d_in, const int* in_sizes, int n_in,
                              void* d_out, int out_size) {
    const float* feats_a = (const float*)d_in[0];
    const float* feats_b = (const float*)d_in[1];
    const float* W       = (const float*)d_in[2];
    const float* bias    = (const float*)d_in[3];
    const int*   ca      = (const int*)d_in[4];
    const int*   cb      = (const int*)d_in[5];
    float*       out     = (float*)d_out;

    // one-time resources (created on the uncaptured correctness call)
    static cudaStream_t s1 = nullptr;
    static cudaEvent_t  evFork = nullptr, evJoin = nullptr;
    if (s1 == nullptr) {
        cudaStreamCreateWithFlags(&s1, cudaStreamNonBlocking);
        cudaEventCreateWithFlags(&evFork, cudaEventDisableTiming);
        cudaEventCreateWithFlags(&evJoin, cudaEventDisableTiming);
    }

    // fork: side stream runs topk + wprep + passthrough under the GEMM
    cudaEventRecord(evFork, 0);
    cudaStreamWaitEvent(s1, evFork, 0);

    topk_part_kernel<<<dim3(NA_ / 128, B_, 4), 128, 0, s1>>>(ca, cb);
    wprep_kernel<<<M_ / 256, 256, 0, s1>>>();
    passthru_kernel<<<M_ * 128 / 256, 256, 0, s1>>>(feats_a, out);
    cudaEventRecord(evJoin, s1);

    // main stream: W fragments, then the fused GEMMs
    prep_frag_kernel<<<256, 256>>>(W);
    mma_gemm<<<dim3(2, 256, 2), 256>>>(feats_a, feats_b, bias);

    // join, then combine (needs GEMM outputs + wprep results)
    cudaStreamWaitEvent(0, evJoin, 0);
    combine_kernel<<<M_ / 2, 256>>>(out);

    (void)in_sizes; (void)n_in; (void)out_size;
}